// round 2
// baseline (speedup 1.0000x reference)
#include <cuda_runtime.h>

#define RNUM 4
#define NNODE 100000
#define NEDGE 1000000
#define DH 128
#define GNUM 256
#define NC 10

// ---------------- static device scratch (no allocations allowed) ----------------
__device__ int   g_cnt_out[RNUM * NNODE];
__device__ int   g_cnt_in [RNUM * NNODE];
__device__ float g_rs_out [RNUM * NNODE];
__device__ float g_rs_in  [RNUM * NNODE];
__device__ int   g_rowstart[RNUM * (NNODE + 1)];
__device__ int   g_cursor [RNUM * NNODE];
__device__ int   g_csr    [RNUM * NEDGE];
__device__ float g_h      [2 * (size_t)NNODE * DH];     // ping-pong hidden states
__device__ float g_m      [(size_t)NNODE * 4 * DH];     // stacked aggregation [N, 512]
__device__ float g_hg     [GNUM * DH];
__device__ int   g_gcnt   [GNUM];

// ---------------- init ----------------
__global__ void k_zero() {
    int i = blockIdx.x * blockDim.x + threadIdx.x;
    if (i < RNUM * NNODE) { g_cnt_out[i] = 0; g_cnt_in[i] = 0; g_cursor[i] = 0; }
    if (i < GNUM * DH) g_hg[i] = 0.f;
    if (i < GNUM) g_gcnt[i] = 0;
}

// ---------------- degree counting ----------------
__global__ void k_count(const int* __restrict__ edges) {
    int i = blockIdx.x * blockDim.x + threadIdx.x;
    if (i >= RNUM * NEDGE) return;
    int r = i / NEDGE, e = i % NEDGE;
    int src = edges[(size_t)r * 2 * NEDGE + e];
    int dst = edges[(size_t)r * 2 * NEDGE + NEDGE + e];
    atomicAdd(&g_cnt_out[r * NNODE + src], 1);
    atomicAdd(&g_cnt_in [r * NNODE + dst], 1);
}

__global__ void k_rs() {
    int i = blockIdx.x * blockDim.x + threadIdx.x;
    if (i >= RNUM * NNODE) return;
    g_rs_out[i] = rsqrtf(fmaxf((float)g_cnt_out[i], 1.f));
    g_rs_in [i] = rsqrtf(fmaxf((float)g_cnt_in [i], 1.f));
}

// ---------------- exclusive prefix sum of in-degrees (one block per relation) ----------------
__global__ void k_scan() {
    int r = blockIdx.x;
    __shared__ int sums[1024];
    const int chunk = (NNODE + 1023) / 1024;
    int t = threadIdx.x;
    int beg = t * chunk;
    int end = min(beg + chunk, NNODE);
    int s = 0;
    for (int i = beg; i < end; i++) s += g_cnt_in[r * NNODE + i];
    sums[t] = s;
    __syncthreads();
    for (int off = 1; off < 1024; off <<= 1) {
        int v = (t >= off) ? sums[t - off] : 0;
        __syncthreads();
        sums[t] += v;
        __syncthreads();
    }
    int excl = (t == 0) ? 0 : sums[t - 1];
    for (int i = beg; i < end; i++) {
        g_rowstart[r * (NNODE + 1) + i] = excl;
        excl += g_cnt_in[r * NNODE + i];
    }
    if (t == 1023) g_rowstart[r * (NNODE + 1) + NNODE] = sums[1023];
}

// ---------------- CSR fill (by destination) ----------------
__global__ void k_csr(const int* __restrict__ edges) {
    int i = blockIdx.x * blockDim.x + threadIdx.x;
    if (i >= RNUM * NEDGE) return;
    int r = i / NEDGE, e = i % NEDGE;
    int src = edges[(size_t)r * 2 * NEDGE + e];
    int dst = edges[(size_t)r * 2 * NEDGE + NEDGE + e];
    int pos = atomicAdd(&g_cursor[r * NNODE + dst], 1);
    g_csr[r * NEDGE + g_rowstart[r * (NNODE + 1) + dst] + pos] = src;
}

// ---------------- aggregation: m[n, r*128 + :] = rs_in * sum_e rs_out[src] * h[src] ----------------
// one warp per node, 4 relations inner loop, float4 per lane (128 floats / 32 lanes)
__global__ void k_agg(const float* __restrict__ ext, int use_ext, int buf) {
    int w = (blockIdx.x * blockDim.x + threadIdx.x) >> 5;
    int lane = threadIdx.x & 31;
    if (w >= NNODE) return;
    const float* hin = use_ext ? ext : (g_h + (size_t)buf * NNODE * DH);
    int n = w;
    #pragma unroll
    for (int r = 0; r < RNUM; r++) {
        int beg = __ldg(&g_rowstart[r * (NNODE + 1) + n]);
        int end = __ldg(&g_rowstart[r * (NNODE + 1) + n + 1]);
        float4 acc = make_float4(0.f, 0.f, 0.f, 0.f);
        for (int e = beg; e < end; e++) {
            int src = __ldg(&g_csr[r * NEDGE + e]);
            float sc = __ldg(&g_rs_out[r * NNODE + src]);
            float4 hv = __ldg((const float4*)(hin + (size_t)src * DH) + lane);
            acc.x += sc * hv.x; acc.y += sc * hv.y;
            acc.z += sc * hv.z; acc.w += sc * hv.w;
        }
        float si = __ldg(&g_rs_in[r * NNODE + n]);
        acc.x *= si; acc.y *= si; acc.z *= si; acc.w *= si;
        ((float4*)(g_m + (size_t)n * (4 * DH) + r * DH))[lane] = acc;
    }
}

// ---------------- fused GEMM: C[N,128] = relu(m[N,512] @ Wstack[512,128] + sum_r b[r]) ----------------
// Wstack is the raw [R, Din, Dh] tensor viewed flat: k = r*128+din maps exactly.
__global__ __launch_bounds__(256) void k_gemm(const float* __restrict__ W,
                                              const float* __restrict__ bias,
                                              int outbuf) {
    __shared__ float As[2][16][128];
    __shared__ float Bs[2][16][128];
    const float* A = g_m;
    float* C = g_h + (size_t)outbuf * NNODE * DH;
    int tid = threadIdx.x;
    int row0 = blockIdx.x * 128;
    int ty = tid >> 4, tx = tid & 15;

    float c[8][8];
    #pragma unroll
    for (int i = 0; i < 8; i++)
        #pragma unroll
        for (int j = 0; j < 8; j++) c[i][j] = 0.f;

    // prologue: load stage 0
    #pragma unroll
    for (int qq = 0; qq < 2; qq++) {
        int q = tid + qq * 256;
        int ar = q >> 2, ac = (q & 3) << 2;
        float4 v = make_float4(0.f, 0.f, 0.f, 0.f);
        int grow = row0 + ar;
        if (grow < NNODE) v = *(const float4*)(A + (size_t)grow * 512 + ac);
        As[0][ac + 0][ar] = v.x; As[0][ac + 1][ar] = v.y;
        As[0][ac + 2][ar] = v.z; As[0][ac + 3][ar] = v.w;
        int br = q >> 5, bc = (q & 31) << 2;
        *(float4*)&Bs[0][br][bc] = *(const float4*)(W + (size_t)br * 128 + bc);
    }
    __syncthreads();

    int s = 0;
    for (int k0 = 0; k0 < 512; k0 += 16) {
        if (k0 + 16 < 512) {
            int ns = s ^ 1;
            #pragma unroll
            for (int qq = 0; qq < 2; qq++) {
                int q = tid + qq * 256;
                int ar = q >> 2, ac = (q & 3) << 2;
                float4 v = make_float4(0.f, 0.f, 0.f, 0.f);
                int grow = row0 + ar;
                if (grow < NNODE) v = *(const float4*)(A + (size_t)grow * 512 + k0 + 16 + ac);
                As[ns][ac + 0][ar] = v.x; As[ns][ac + 1][ar] = v.y;
                As[ns][ac + 2][ar] = v.z; As[ns][ac + 3][ar] = v.w;
                int br = q >> 5, bc = (q & 31) << 2;
                *(float4*)&Bs[ns][br][bc] = *(const float4*)(W + (size_t)(k0 + 16 + br) * 128 + bc);
            }
        }
        #pragma unroll
        for (int kk = 0; kk < 16; kk++) {
            float a[8], b[8];
            *(float4*)&a[0] = *(const float4*)&As[s][kk][ty * 8];
            *(float4*)&a[4] = *(const float4*)&As[s][kk][ty * 8 + 4];
            *(float4*)&b[0] = *(const float4*)&Bs[s][kk][tx * 8];
            *(float4*)&b[4] = *(const float4*)&Bs[s][kk][tx * 8 + 4];
            #pragma unroll
            for (int i = 0; i < 8; i++)
                #pragma unroll
                for (int j = 0; j < 8; j++)
                    c[i][j] += a[i] * b[j];
        }
        __syncthreads();
        s ^= 1;
    }

    float bsum[8];
    #pragma unroll
    for (int j = 0; j < 8; j++) {
        int col = tx * 8 + j;
        bsum[j] = bias[col] + bias[DH + col] + bias[2 * DH + col] + bias[3 * DH + col];
    }
    #pragma unroll
    for (int i = 0; i < 8; i++) {
        int grow = row0 + ty * 8 + i;
        if (grow < NNODE) {
            float4 v0, v1;
            v0.x = fmaxf(c[i][0] + bsum[0], 0.f);
            v0.y = fmaxf(c[i][1] + bsum[1], 0.f);
            v0.z = fmaxf(c[i][2] + bsum[2], 0.f);
            v0.w = fmaxf(c[i][3] + bsum[3], 0.f);
            v1.x = fmaxf(c[i][4] + bsum[4], 0.f);
            v1.y = fmaxf(c[i][5] + bsum[5], 0.f);
            v1.z = fmaxf(c[i][6] + bsum[6], 0.f);
            v1.w = fmaxf(c[i][7] + bsum[7], 0.f);
            *(float4*)(C + (size_t)grow * DH + tx * 8)     = v0;
            *(float4*)(C + (size_t)grow * DH + tx * 8 + 4) = v1;
        }
    }
}

// ---------------- avg pooling over sorted graph_ids (segmented, few atomics) ----------------
__global__ void k_pool(const int* __restrict__ gid, int buf) {
    const float* h = g_h + (size_t)buf * NNODE * DH;
    int nb = gridDim.x;
    int chunk = (NNODE + nb - 1) / nb;
    int beg = blockIdx.x * chunk;
    int end = min(beg + chunk, NNODE);
    if (beg >= end) return;
    int f = threadIdx.x;
    int cur = gid[beg];
    float acc = 0.f; int cnt = 0;
    for (int i = beg; i < end; i++) {
        int g = gid[i];
        if (g != cur) {
            atomicAdd(&g_hg[cur * DH + f], acc);
            if (f == 0) atomicAdd(&g_gcnt[cur], cnt);
            acc = 0.f; cnt = 0; cur = g;
        }
        acc += h[(size_t)i * DH + f];
        cnt++;
    }
    atomicAdd(&g_hg[cur * DH + f], acc);
    if (f == 0) atomicAdd(&g_gcnt[cur], cnt);
}

// ---------------- classifier: out[g] = (hg[g]/count) @ Wc + bc ----------------
__global__ void k_cls(const float* __restrict__ Wc, const float* __restrict__ bc,
                      float* __restrict__ out) {
    int g = blockIdx.x;
    __shared__ float row[DH];
    int t = threadIdx.x;
    float inv = 1.f / fmaxf((float)g_gcnt[g], 1.f);
    row[t] = g_hg[g * DH + t] * inv;
    __syncthreads();
    if (t < NC) {
        float s = bc[t];
        #pragma unroll 16
        for (int k = 0; k < DH; k++) s += row[k] * Wc[k * NC + t];
        out[g * NC + t] = s;
    }
}

// ---------------- launch ----------------
extern "C" void kernel_launch(void* const* d_in, const int* in_sizes, int n_in,
                              void* d_out, int out_size) {
    const float* features = (const float*)d_in[0];
    const int*   edges    = (const int*)d_in[1];
    const int*   gid      = (const int*)d_in[2];
    const float* W0       = (const float*)d_in[3];
    const float* b0       = (const float*)d_in[4];
    const float* Wl       = (const float*)d_in[5];
    const float* bl       = (const float*)d_in[6];
    const float* Wc       = (const float*)d_in[7];
    const float* bc       = (const float*)d_in[8];
    float* out = (float*)d_out;

    // graph structure (recomputed each launch — no caching allowed)
    k_zero <<<(RNUM * NNODE + 255) / 256, 256>>>();
    k_count<<<(RNUM * NEDGE + 255) / 256, 256>>>(edges);
    k_rs   <<<(RNUM * NNODE + 255) / 256, 256>>>();
    k_scan <<<RNUM, 1024>>>();
    k_csr  <<<(RNUM * NEDGE + 255) / 256, 256>>>(edges);

    const int aggBlocks  = (NNODE * 32 + 255) / 256;  // one warp per node
    const int gemmBlocks = (NNODE + 127) / 128;

    // layer 0: features -> h[0]
    k_agg <<<aggBlocks, 256>>>(features, 1, 0);
    k_gemm<<<gemmBlocks, 256>>>(W0, b0, 0);
    // layer 1: h[0] -> h[1]
    k_agg <<<aggBlocks, 256>>>(nullptr, 0, 0);
    k_gemm<<<gemmBlocks, 256>>>(Wl, bl, 1);
    // layer 2: h[1] -> h[0]
    k_agg <<<aggBlocks, 256>>>(nullptr, 0, 1);
    k_gemm<<<gemmBlocks, 256>>>(Wl + 4 * DH * DH, bl + 4 * DH, 0);

    // pooling + classifier
    k_pool<<<784, DH>>>(gid, 0);
    k_cls <<<GNUM, DH>>>(Wc, bc, out);
}

// round 3
// speedup vs baseline: 1.5207x; 1.5207x over previous
#include <cuda_runtime.h>

#define RNUM 4
#define NNODE 100000
#define NEDGE 1000000
#define DH 128
#define GNUM 256
#define NC 10
#define NB 98   // ceil(NNODE/1024)

// ---------------- static device scratch (no allocations allowed) ----------------
__device__ int   g_cnt_out[RNUM * NNODE];
__device__ int   g_cnt_in [RNUM * NNODE];
__device__ float g_rs_out [RNUM * NNODE];
__device__ float g_rs_in  [RNUM * NNODE];
__device__ int   g_rowstart[RNUM * (NNODE + 1)];
__device__ int   g_cursor [RNUM * NNODE];
__device__ int   g_csr    [RNUM * NEDGE];
__device__ int   g_bsum   [RNUM * NB];
__device__ float g_h      [2 * (size_t)NNODE * DH];     // ping-pong hidden states
__device__ float g_m      [(size_t)NNODE * 4 * DH];     // stacked aggregation [N, 512]
__device__ float g_hg     [GNUM * DH];
__device__ int   g_gcnt   [GNUM];

// ---------------- init ----------------
__global__ void k_zero() {
    int i = blockIdx.x * blockDim.x + threadIdx.x;
    if (i < RNUM * NNODE) { g_cnt_out[i] = 0; g_cnt_in[i] = 0; g_cursor[i] = 0; }
    if (i < GNUM * DH) g_hg[i] = 0.f;
    if (i < GNUM) g_gcnt[i] = 0;
}

// ---------------- degree counting ----------------
__global__ void k_count(const int* __restrict__ edges) {
    int i = blockIdx.x * blockDim.x + threadIdx.x;
    if (i >= RNUM * NEDGE) return;
    int r = i / NEDGE, e = i % NEDGE;
    int src = edges[(size_t)r * 2 * NEDGE + e];
    int dst = edges[(size_t)r * 2 * NEDGE + NEDGE + e];
    atomicAdd(&g_cnt_out[r * NNODE + src], 1);
    atomicAdd(&g_cnt_in [r * NNODE + dst], 1);
}

__global__ void k_rs() {
    int i = blockIdx.x * blockDim.x + threadIdx.x;
    if (i >= RNUM * NNODE) return;
    g_rs_out[i] = rsqrtf(fmaxf((float)g_cnt_out[i], 1.f));
    g_rs_in [i] = rsqrtf(fmaxf((float)g_cnt_in [i], 1.f));
}

// ---------------- parallel 3-phase exclusive scan of in-degrees ----------------
__global__ void k_scanA() {
    int r = blockIdx.y;
    int i = blockIdx.x * 1024 + threadIdx.x;
    int v = (i < NNODE) ? g_cnt_in[r * NNODE + i] : 0;
    __shared__ int ws[32];
    int lane = threadIdx.x & 31, wid = threadIdx.x >> 5;
    #pragma unroll
    for (int o = 16; o; o >>= 1) v += __shfl_down_sync(~0u, v, o);
    if (!lane) ws[wid] = v;
    __syncthreads();
    if (!wid) {
        int s = ws[lane];
        #pragma unroll
        for (int o = 16; o; o >>= 1) s += __shfl_down_sync(~0u, s, o);
        if (!lane) g_bsum[r * NB + blockIdx.x] = s;
    }
}

__global__ void k_scanB() {
    int r = blockIdx.x;
    if (threadIdx.x == 0) {
        int acc = 0;
        for (int b = 0; b < NB; b++) { int v = g_bsum[r * NB + b]; g_bsum[r * NB + b] = acc; acc += v; }
        g_rowstart[r * (NNODE + 1) + NNODE] = acc;
    }
}

__global__ void k_scanC() {
    int r = blockIdx.y;
    int i = blockIdx.x * 1024 + threadIdx.x;
    int v = (i < NNODE) ? g_cnt_in[r * NNODE + i] : 0;
    int lane = threadIdx.x & 31, wid = threadIdx.x >> 5;
    int incl = v;
    #pragma unroll
    for (int o = 1; o < 32; o <<= 1) { int t = __shfl_up_sync(~0u, incl, o); if (lane >= o) incl += t; }
    __shared__ int ws[32];
    if (lane == 31) ws[wid] = incl;
    __syncthreads();
    if (wid == 0) {
        int s = ws[lane];
        #pragma unroll
        for (int o = 1; o < 32; o <<= 1) { int t = __shfl_up_sync(~0u, s, o); if (lane >= o) s += t; }
        ws[lane] = s;
    }
    __syncthreads();
    int base = g_bsum[r * NB + blockIdx.x] + (wid ? ws[wid - 1] : 0);
    if (i < NNODE) g_rowstart[r * (NNODE + 1) + i] = base + incl - v;
}

// ---------------- CSR fill (by destination) ----------------
__global__ void k_csr(const int* __restrict__ edges) {
    int i = blockIdx.x * blockDim.x + threadIdx.x;
    if (i >= RNUM * NEDGE) return;
    int r = i / NEDGE, e = i % NEDGE;
    int src = edges[(size_t)r * 2 * NEDGE + e];
    int dst = edges[(size_t)r * 2 * NEDGE + NEDGE + e];
    int pos = atomicAdd(&g_cursor[r * NNODE + dst], 1);
    g_csr[r * NEDGE + g_rowstart[r * (NNODE + 1) + dst] + pos] = src;
}

// ---------------- aggregation: m[n, r*128 + :] = rs_in * sum_e rs_out[src] * h[src] ----------------
__global__ void k_agg(const float* __restrict__ ext, int use_ext, int buf) {
    int w = (blockIdx.x * blockDim.x + threadIdx.x) >> 5;
    int lane = threadIdx.x & 31;
    if (w >= NNODE) return;
    const float* hin = use_ext ? ext : (g_h + (size_t)buf * NNODE * DH);
    int n = w;
    #pragma unroll
    for (int r = 0; r < RNUM; r++) {
        int beg = __ldg(&g_rowstart[r * (NNODE + 1) + n]);
        int end = __ldg(&g_rowstart[r * (NNODE + 1) + n + 1]);
        float4 acc = make_float4(0.f, 0.f, 0.f, 0.f);
        for (int e = beg; e < end; e++) {
            int src = __ldg(&g_csr[r * NEDGE + e]);
            float sc = __ldg(&g_rs_out[r * NNODE + src]);
            float4 hv = __ldg((const float4*)(hin + (size_t)src * DH) + lane);
            acc.x += sc * hv.x; acc.y += sc * hv.y;
            acc.z += sc * hv.z; acc.w += sc * hv.w;
        }
        float si = __ldg(&g_rs_in[r * NNODE + n]);
        acc.x *= si; acc.y *= si; acc.z *= si; acc.w *= si;
        ((float4*)(g_m + (size_t)n * (4 * DH) + r * DH))[lane] = acc;
    }
}

// ---------------- tf32 tensor-core GEMM: C = relu(m[N,512] @ Wstack[512,128] + sum_r b[r]) ----------------
__device__ __forceinline__ unsigned f2tf(float x) {
    unsigned r;
    asm("cvt.rna.tf32.f32 %0, %1;" : "=r"(r) : "f"(x));
    return r;
}

__device__ __forceinline__ void mma_tf32(float c[4], unsigned a0, unsigned a1, unsigned a2,
                                         unsigned a3, unsigned b0, unsigned b1) {
    asm volatile("mma.sync.aligned.m16n8k8.row.col.f32.tf32.tf32.f32 "
                 "{%0,%1,%2,%3}, {%4,%5,%6,%7}, {%8,%9}, {%0,%1,%2,%3};"
                 : "+f"(c[0]), "+f"(c[1]), "+f"(c[2]), "+f"(c[3])
                 : "r"(a0), "r"(a1), "r"(a2), "r"(a3), "r"(b0), "r"(b1));
}

__global__ __launch_bounds__(256) void k_gemm_tc(const float* __restrict__ W,
                                                 const float* __restrict__ bias,
                                                 int outbuf) {
    __shared__ unsigned As[2][16][132];   // [k][row] tf32 bits
    __shared__ unsigned Bs[2][16][132];   // [k][col] tf32 bits
    const float* A = g_m;
    float* C = g_h + (size_t)outbuf * NNODE * DH;
    int tid = threadIdx.x;
    int row0 = blockIdx.x * 128;
    int warp = tid >> 5, lane = tid & 31;
    int warpM = warp >> 2, warpN = warp & 3;   // 2 x 4 warp grid
    int qr = lane >> 2, qc = lane & 3;

    float c[4][4][4];
    #pragma unroll
    for (int m = 0; m < 4; m++)
        #pragma unroll
        for (int n = 0; n < 4; n++)
            #pragma unroll
            for (int k = 0; k < 4; k++) c[m][n][k] = 0.f;

    // prologue: stage 0
    #pragma unroll
    for (int qq = 0; qq < 2; qq++) {
        int q = tid + qq * 256;
        int ar = q >> 2, ac = (q & 3) << 2;
        float4 v = make_float4(0.f, 0.f, 0.f, 0.f);
        int grow = row0 + ar;
        if (grow < NNODE) v = *(const float4*)(A + (size_t)grow * 512 + ac);
        As[0][ac + 0][ar] = f2tf(v.x); As[0][ac + 1][ar] = f2tf(v.y);
        As[0][ac + 2][ar] = f2tf(v.z); As[0][ac + 3][ar] = f2tf(v.w);
        int br = q >> 5, bc = (q & 31) << 2;
        float4 w = *(const float4*)(W + (size_t)br * 128 + bc);
        uint4 u; u.x = f2tf(w.x); u.y = f2tf(w.y); u.z = f2tf(w.z); u.w = f2tf(w.w);
        *(uint4*)&Bs[0][br][bc] = u;
    }
    __syncthreads();

    int s = 0;
    for (int k0 = 0; k0 < 512; k0 += 16) {
        if (k0 + 16 < 512) {
            int ns = s ^ 1;
            #pragma unroll
            for (int qq = 0; qq < 2; qq++) {
                int q = tid + qq * 256;
                int ar = q >> 2, ac = (q & 3) << 2;
                float4 v = make_float4(0.f, 0.f, 0.f, 0.f);
                int grow = row0 + ar;
                if (grow < NNODE) v = *(const float4*)(A + (size_t)grow * 512 + k0 + 16 + ac);
                As[ns][ac + 0][ar] = f2tf(v.x); As[ns][ac + 1][ar] = f2tf(v.y);
                As[ns][ac + 2][ar] = f2tf(v.z); As[ns][ac + 3][ar] = f2tf(v.w);
                int br = q >> 5, bc = (q & 31) << 2;
                float4 w = *(const float4*)(W + (size_t)(k0 + 16 + br) * 128 + bc);
                uint4 u; u.x = f2tf(w.x); u.y = f2tf(w.y); u.z = f2tf(w.z); u.w = f2tf(w.w);
                *(uint4*)&Bs[ns][br][bc] = u;
            }
        }
        #pragma unroll
        for (int kk0 = 0; kk0 < 16; kk0 += 8) {
            unsigned bfr[4][2];
            #pragma unroll
            for (int n = 0; n < 4; n++) {
                int col = warpN * 32 + n * 8 + qr;
                bfr[n][0] = Bs[s][kk0 + qc][col];
                bfr[n][1] = Bs[s][kk0 + qc + 4][col];
            }
            #pragma unroll
            for (int m = 0; m < 4; m++) {
                int row = warpM * 64 + m * 16;
                unsigned a0 = As[s][kk0 + qc][row + qr];
                unsigned a1 = As[s][kk0 + qc][row + qr + 8];
                unsigned a2 = As[s][kk0 + qc + 4][row + qr];
                unsigned a3 = As[s][kk0 + qc + 4][row + qr + 8];
                #pragma unroll
                for (int n = 0; n < 4; n++)
                    mma_tf32(c[m][n], a0, a1, a2, a3, bfr[n][0], bfr[n][1]);
            }
        }
        __syncthreads();
        s ^= 1;
    }

    // epilogue: bias-sum + relu, float2 stores
    #pragma unroll
    for (int n = 0; n < 4; n++) {
        int gc = warpN * 32 + n * 8 + 2 * qc;
        float b0v = bias[gc]     + bias[DH + gc]     + bias[2 * DH + gc]     + bias[3 * DH + gc];
        float b1v = bias[gc + 1] + bias[DH + gc + 1] + bias[2 * DH + gc + 1] + bias[3 * DH + gc + 1];
        #pragma unroll
        for (int m = 0; m < 4; m++) {
            int gr0 = row0 + warpM * 64 + m * 16 + qr;
            if (gr0 < NNODE) {
                float2 v; v.x = fmaxf(c[m][n][0] + b0v, 0.f); v.y = fmaxf(c[m][n][1] + b1v, 0.f);
                *(float2*)(C + (size_t)gr0 * DH + gc) = v;
            }
            int gr1 = gr0 + 8;
            if (gr1 < NNODE) {
                float2 v; v.x = fmaxf(c[m][n][2] + b0v, 0.f); v.y = fmaxf(c[m][n][3] + b1v, 0.f);
                *(float2*)(C + (size_t)gr1 * DH + gc) = v;
            }
        }
    }
}

// ---------------- avg pooling over sorted graph_ids ----------------
__global__ void k_pool(const int* __restrict__ gid, int buf) {
    const float* h = g_h + (size_t)buf * NNODE * DH;
    int nb = gridDim.x;
    int chunk = (NNODE + nb - 1) / nb;
    int beg = blockIdx.x * chunk;
    int end = min(beg + chunk, NNODE);
    if (beg >= end) return;
    int f = threadIdx.x;
    int cur = gid[beg];
    float acc = 0.f; int cnt = 0;
    for (int i = beg; i < end; i++) {
        int g = gid[i];
        if (g != cur) {
            atomicAdd(&g_hg[cur * DH + f], acc);
            if (f == 0) atomicAdd(&g_gcnt[cur], cnt);
            acc = 0.f; cnt = 0; cur = g;
        }
        acc += h[(size_t)i * DH + f];
        cnt++;
    }
    atomicAdd(&g_hg[cur * DH + f], acc);
    if (f == 0) atomicAdd(&g_gcnt[cur], cnt);
}

// ---------------- classifier ----------------
__global__ void k_cls(const float* __restrict__ Wc, const float* __restrict__ bc,
                      float* __restrict__ out) {
    int g = blockIdx.x;
    __shared__ float row[DH];
    int t = threadIdx.x;
    float inv = 1.f / fmaxf((float)g_gcnt[g], 1.f);
    row[t] = g_hg[g * DH + t] * inv;
    __syncthreads();
    if (t < NC) {
        float s = bc[t];
        #pragma unroll 16
        for (int k = 0; k < DH; k++) s += row[k] * Wc[k * NC + t];
        out[g * NC + t] = s;
    }
}

// ---------------- launch ----------------
extern "C" void kernel_launch(void* const* d_in, const int* in_sizes, int n_in,
                              void* d_out, int out_size) {
    const float* features = (const float*)d_in[0];
    const int*   edges    = (const int*)d_in[1];
    const int*   gid      = (const int*)d_in[2];
    const float* W0       = (const float*)d_in[3];
    const float* b0       = (const float*)d_in[4];
    const float* Wl       = (const float*)d_in[5];
    const float* bl       = (const float*)d_in[6];
    const float* Wc       = (const float*)d_in[7];
    const float* bc       = (const float*)d_in[8];
    float* out = (float*)d_out;

    // graph structure (recomputed each launch — no caching allowed)
    k_zero <<<(RNUM * NNODE + 255) / 256, 256>>>();
    k_count<<<(RNUM * NEDGE + 255) / 256, 256>>>(edges);
    k_rs   <<<(RNUM * NNODE + 255) / 256, 256>>>();
    k_scanA<<<dim3(NB, RNUM), 1024>>>();
    k_scanB<<<RNUM, 32>>>();
    k_scanC<<<dim3(NB, RNUM), 1024>>>();
    k_csr  <<<(RNUM * NEDGE + 255) / 256, 256>>>(edges);

    const int aggBlocks  = (NNODE * 32 + 255) / 256;  // one warp per node
    const int gemmBlocks = (NNODE + 127) / 128;

    // layer 0: features -> h[0]
    k_agg    <<<aggBlocks, 256>>>(features, 1, 0);
    k_gemm_tc<<<gemmBlocks, 256>>>(W0, b0, 0);
    // layer 1: h[0] -> h[1]
    k_agg    <<<aggBlocks, 256>>>(nullptr, 0, 0);
    k_gemm_tc<<<gemmBlocks, 256>>>(Wl, bl, 1);
    // layer 2: h[1] -> h[0]
    k_agg    <<<aggBlocks, 256>>>(nullptr, 0, 1);
    k_gemm_tc<<<gemmBlocks, 256>>>(Wl + 4 * DH * DH, bl + 4 * DH, 0);

    // pooling + classifier
    k_pool<<<784, DH>>>(gid, 0);
    k_cls <<<GNUM, DH>>>(Wc, bc, out);
}